// round 17
// baseline (speedup 1.0000x reference)
#include <cuda_runtime.h>
#include <cstddef>
#include <cstdint>

#define TLEN 512
#define NB   64
#define UDIM 256
#define GDIM 768
#define EDIM 300
#define CDIM 20
#define KP   260   // rk smem row pad: lane stride 1040B -> conflict-free LDS.128

__device__ float g_xw[(size_t)2 * NB * TLEN * GDIM];   // [dir][b*T+t][g]
__device__ float g_h1[(size_t)NB * TLEN * 2 * UDIM];   // [b*T+t][2U]
__device__ float g_hbuf[2 * 2 * 8 * 8 * UDIM];         // [par][dir][bg][8][U]
__device__ float g_h2[NB * 2 * UDIM];
__device__ unsigned g_cnt[1024];                       // [layer][16 groups * 32 pad]

__device__ __forceinline__ unsigned long long ffma2(unsigned long long a,
                                                    unsigned long long b,
                                                    unsigned long long c) {
    unsigned long long d;
    asm("fma.rn.f32x2 %0,%1,%2,%3;" : "=l"(d) : "l"(a), "l"(b), "l"(c));
    return d;
}
__device__ __forceinline__ unsigned long long dup2(float x) {
    unsigned long long d;
    asm("mov.b64 %0,{%1,%1};" : "=l"(d) : "r"(__float_as_uint(x)));
    return d;
}
union F4U { float4 v; float f[4]; unsigned long long u[2]; };

__device__ __forceinline__ void red_release_gpu(unsigned* p, unsigned v) {
    asm volatile("red.release.gpu.global.add.u32 [%0], %1;" :: "l"(p), "r"(v) : "memory");
}
__device__ __forceinline__ unsigned ld_acquire_gpu(const unsigned* p) {
    unsigned v;
    asm volatile("ld.acquire.gpu.global.u32 %0, [%1];" : "=r"(v) : "l"(p) : "memory");
    return v;
}

// inf-safe fast activations (MUFU ex2/rcp based)
__device__ __forceinline__ float fsig(float x) {
    return __fdividef(1.0f, 1.0f + __expf(-x));
}
__device__ __forceinline__ float ftanh(float x) {
    return 1.0f - __fdividef(2.0f, 1.0f + __expf(2.0f * x));
}

// ================= GEMM: 2-stage register-prefetch pipeline =================
#define BM 128
#define BN 128
#define BK 8

__global__ __launch_bounds__(256, 2)
void gemm_kernel(int mode, const int* __restrict__ gidx, const float* __restrict__ emb,
                 const float* __restrict__ Wf, const float* __restrict__ Wb,
                 const float* __restrict__ bf, const float* __restrict__ bb,
                 int K, int czoff)
{
    const int tid = threadIdx.x;
    if (blockIdx.x == 0 && blockIdx.y == 0 && blockIdx.z == 0) {   // reset rec barrier bank
        g_cnt[czoff + tid] = 0u; g_cnt[czoff + 256 + tid] = 0u;
    }
    const int dir = blockIdx.z;
    const float* __restrict__ W    = dir ? Wb : Wf;
    const float* __restrict__ bias = dir ? bb : bf;
    float* outp = g_xw + (size_t)dir * NB * TLEN * GDIM;
    const int bm = blockIdx.y * BM, bn = blockIdx.x * BN;

    __shared__ float As[BK][BM + 4];
    __shared__ float Bs[BK][BN];

    const int a_m = tid >> 1, a_k = (tid & 1) * 4;
    const int b_k = tid >> 5, b_n = (tid & 31) * 4;
    const int tx = tid & 15, ty = tid >> 4;

    const float* arow = mode ? (g_h1 + (size_t)(bm + a_m) * (2 * UDIM))
                             : (emb + (size_t)gidx[bm + a_m] * EDIM);

    auto loadA = [&](int k0, F4U& a) {
        if (k0 + a_k + 4 <= K) {
            a.v = *(const float4*)(arow + k0 + a_k);
        } else {
#pragma unroll
            for (int i = 0; i < 4; i++) {
                int kk = k0 + a_k + i;
                a.f[i] = (kk < K) ? arow[kk] : 0.0f;
            }
        }
    };
    auto loadB = [&](int k0, F4U& b) {
        int kk = k0 + b_k;
        b.v = make_float4(0.f, 0.f, 0.f, 0.f);
        if (kk < K) b.v = *(const float4*)(W + (size_t)kk * GDIM + bn + b_n);
    };
    auto stsTile = [&](const F4U& a, const F4U& b) {
        As[a_k + 0][a_m] = a.f[0]; As[a_k + 1][a_m] = a.f[1];
        As[a_k + 2][a_m] = a.f[2]; As[a_k + 3][a_m] = a.f[3];
        *(float4*)&Bs[b_k][b_n] = b.v;
    };

    unsigned long long acc[8][4];
#pragma unroll
    for (int i = 0; i < 8; i++)
#pragma unroll
        for (int j = 0; j < 4; j++) acc[i][j] = 0ull;

    {
        F4U a0, b0;
        loadA(0, a0); loadB(0, b0);
        stsTile(a0, b0);
    }
    __syncthreads();

    int k0 = 0;
    for (;;) {
        const int k1 = k0 + BK;
        const bool more = (k1 < K);
        F4U anx, bnx;
        if (more) { loadA(k1, anx); loadB(k1, bnx); }   // prefetch next (hidden)

#pragma unroll
        for (int kk = 0; kk < BK; kk++) {
            F4U a0, a1, b0, b1;
            a0.v = *(const float4*)&As[kk][ty * 4];
            a1.v = *(const float4*)&As[kk][64 + ty * 4];
            b0.v = *(const float4*)&Bs[kk][tx * 4];
            b1.v = *(const float4*)&Bs[kk][64 + tx * 4];
            unsigned long long ap[8];
            unsigned long long bp[4] = { b0.u[0], b0.u[1], b1.u[0], b1.u[1] };
#pragma unroll
            for (int i = 0; i < 4; i++) { ap[i] = dup2(a0.f[i]); ap[4 + i] = dup2(a1.f[i]); }
#pragma unroll
            for (int i = 0; i < 8; i++)
#pragma unroll
                for (int j = 0; j < 4; j++)
                    acc[i][j] = ffma2(ap[i], bp[j], acc[i][j]);
        }
        if (!more) break;
        __syncthreads();
        stsTile(anx, bnx);
        __syncthreads();
        k0 = k1;
    }

#pragma unroll
    for (int i = 0; i < 8; i++) {
        int m = bm + ((i < 4) ? (ty * 4 + i) : (64 + ty * 4 + i - 4));
        float* orow = outp + (size_t)m * GDIM + bn;
#pragma unroll
        for (int j = 0; j < 4; j++) {
            int c = (j < 2) ? (tx * 4 + j * 2) : (64 + tx * 4 + (j - 2) * 2);
            F4U t; t.u[0] = acc[i][j];
            float2 r;
            r.x = t.f[0] + bias[bn + c];
            r.y = t.f[1] + bias[bn + c + 1];
            *(float2*)(orow + c) = r;
        }
    }
}

// ===== Recurrence v8: fwd+bwd chains interleaved in one CTA ================
// 64 CTAs = batch-group(8) x unit-slice(8); R14's 256-thread layout per chain:
// kq(4 k-quarters) x bq(2 batch-quads) x j(32 units).
// Both rk slices in smem (225KB total). Chain F's exchange hides under chain
// B's matvec; polls batched at P4 (cpF drained, cpB skew overlaps gates B).
#define RED_F (3 * 2 * 32 * 12)
#define REC_SMEM ((2 * 96 * KP + 2 * 2048 + RED_F) * 4)

__device__ __forceinline__ void rec_matvec(
    const float* rzp, const float* rrp, const float* rhp, const float* hpb,
    float* red, int kq, int bq, int j, float* sz, float* sr, float* sh)
{
    unsigned long long az[4], ar[4], ah[4];
#pragma unroll
    for (int i = 0; i < 4; i++) { az[i] = 0ull; ar[i] = 0ull; ah[i] = 0ull; }
#pragma unroll 4
    for (int k = 0; k < 64; k += 4) {
        F4U vz, vr, vh;
        vz.v = *(const float4*)(rzp + k);
        vr.v = *(const float4*)(rrp + k);
        vh.v = *(const float4*)(rhp + k);
#pragma unroll
        for (int i = 0; i < 4; i++) {
            F4U hv; hv.v = *(const float4*)(hpb + i * 256 + k);
            az[i] = ffma2(vz.u[0], hv.u[0], az[i]);
            az[i] = ffma2(vz.u[1], hv.u[1], az[i]);
            ar[i] = ffma2(vr.u[0], hv.u[0], ar[i]);
            ar[i] = ffma2(vr.u[1], hv.u[1], ar[i]);
            ah[i] = ffma2(vh.u[0], hv.u[0], ah[i]);
            ah[i] = ffma2(vh.u[1], hv.u[1], ah[i]);
        }
    }
#pragma unroll
    for (int i = 0; i < 4; i++) {
        F4U a; a.u[0] = az[i]; sz[i] = a.f[0] + a.f[1];
        a.u[0] = ar[i];        sr[i] = a.f[0] + a.f[1];
        a.u[0] = ah[i];        sh[i] = a.f[0] + a.f[1];
    }
    if (kq != 0) {
        float* rp = red + (((kq - 1) * 2 + bq) * 32 + j) * 12;
        *(float4*)(rp + 0) = make_float4(sz[0], sz[1], sz[2], sz[3]);
        *(float4*)(rp + 4) = make_float4(sr[0], sr[1], sr[2], sr[3]);
        *(float4*)(rp + 8) = make_float4(sh[0], sh[1], sh[2], sh[3]);
    }
}

__global__ __launch_bounds__(256, 1)
void rec_kernel(const float* __restrict__ rkf, const float* __restrict__ rkb,
                const float* __restrict__ rbf, const float* __restrict__ rbb,
                int layer, int coff)
{
    extern __shared__ float sm[];
    float* rkF = sm;                        // [96][KP]
    float* rkB = sm + 96 * KP;              // [96][KP]
    float* hF  = sm + 2 * 96 * KP;          // [8][256]
    float* hB  = hF + 2048;                 // [8][256]
    float* red = hB + 2048;                 // [3][2][32][12]
    const int blk = blockIdx.x, bg = blk >> 3, us = blk & 7;
    const int tid = threadIdx.x;
    const int kq = tid >> 6, bq = (tid >> 5) & 1, j = tid & 31;

    for (int i = tid; i < 96 * 256; i += 256) {
        int k = i / 96, c = i - k * 96;
        int col = (size_t)0 + (c >> 5) * UDIM + us * 32 + (c & 31);
        rkF[c * KP + k] = rkf[(size_t)k * GDIM + col];
        rkB[c * KP + k] = rkb[(size_t)k * GDIM + col];
    }
    for (int i = tid; i < 2048; i += 256) { hF[i] = 0.0f; hB[i] = 0.0f; }
    __syncthreads();

    const int u = us * 32 + j;
    const int kb = kq * 64;
    const float rbzF = rbf[u], rbrF = rbf[UDIM + u], rbhF = rbf[2 * UDIM + u];
    const float rbzB = rbb[u], rbrB = rbb[UDIM + u], rbhB = rbb[2 * UDIM + u];
    const float* xwdF = g_xw;
    const float* xwdB = g_xw + (size_t)NB * TLEN * GDIM;
    unsigned* cpF = g_cnt + coff + (0 * 8 + bg) * 32;
    unsigned* cpB = g_cnt + coff + (1 * 8 + bg) * 32;
    const float* rzF = rkF + (size_t)j * KP + kb;
    const float* rrF = rkF + (size_t)(32 + j) * KP + kb;
    const float* rhF = rkF + (size_t)(64 + j) * KP + kb;
    const float* rzB = rkB + (size_t)j * KP + kb;
    const float* rrB = rkB + (size_t)(32 + j) * KP + kb;
    const float* rhB = rkB + (size_t)(64 + j) * KP + kb;
    const float* hpbF = hF + (bq * 4) * 256 + kb;
    const float* hpbB = hB + (bq * 4) * 256 + kb;

    float* gbF0 = g_hbuf + ((0 * 2 + 0) * 8 + bg) * (8 * UDIM);
    float* gbF1 = g_hbuf + ((1 * 2 + 0) * 8 + bg) * (8 * UDIM);
    float* gbB0 = g_hbuf + ((0 * 2 + 1) * 8 + bg) * (8 * UDIM);
    float* gbB1 = g_hbuf + ((1 * 2 + 1) * 8 + bg) * (8 * UDIM);

    // per-warp reload slice (R14 mapping): 2 float4 per thread per chain
    const int qi0 = (bq * 4 + (j >> 4)) * 64 + kq * 16 + (j & 15);
    const int qi1 = qi0 + 2 * 64;

    float hprevF[4] = {0.f, 0.f, 0.f, 0.f};
    float hprevB[4] = {0.f, 0.f, 0.f, 0.f};

    for (int s = 0; s < TLEN; s++) {
        const int tF = s, tB = TLEN - 1 - s;
        float sz[4], sr[4], sh[4];

        // ---------------- chain F ----------------
        float xz[4], xr[4], xh[4];
        if (kq == 0) {
#pragma unroll
            for (int i = 0; i < 4; i++) {
                const float* xr0 = xwdF + ((size_t)(bg * 8 + bq * 4 + i) * TLEN + tF) * GDIM;
                xz[i] = __ldg(xr0 + u);
                xr[i] = __ldg(xr0 + UDIM + u);
                xh[i] = __ldg(xr0 + 2 * UDIM + u);
            }
        }
        rec_matvec(rzF, rrF, rhF, hpbF, red, kq, bq, j, sz, sr, sh);
        __syncthreads();   // BAR1

        if (kq == 0) {
#pragma unroll
            for (int q = 0; q < 3; q++) {
                const float* rp = red + ((q * 2 + bq) * 32 + j) * 12;
                float4 a = *(const float4*)(rp + 0);
                float4 b = *(const float4*)(rp + 4);
                float4 c = *(const float4*)(rp + 8);
                sz[0] += a.x; sz[1] += a.y; sz[2] += a.z; sz[3] += a.w;
                sr[0] += b.x; sr[1] += b.y; sr[2] += b.z; sr[3] += b.w;
                sh[0] += c.x; sh[1] += c.y; sh[2] += c.z; sh[3] += c.w;
            }
            float* gb = (s & 1) ? gbF1 : gbF0;
#pragma unroll
            for (int i = 0; i < 4; i++) {
                const int bL = bq * 4 + i;
                float z = fsig(xz[i] + rbzF + sz[i]);
                float r = fsig(xr[i] + rbrF + sr[i]);
                float hh = ftanh(xh[i] + rbhF + r * sh[i]);
                float hn = z * hprevF[i] + (1.f - z) * hh;
                hprevF[i] = hn;
                gb[bL * UDIM + u] = hn;
                if (layer == 1)
                    g_h1[((size_t)(bg * 8 + bL) * TLEN + tF) * (2 * UDIM) + u] = hn;
                else if (s == TLEN - 1)
                    g_h2[(bg * 8 + bL) * 2 * UDIM + u] = hn;
            }
            asm volatile("bar.sync 1, 64;" ::: "memory");
            if (tid == 0) red_release_gpu(cpF, 1u);
        }
        __syncthreads();   // BAR2

        // ---------------- chain B ----------------
        if (kq == 0) {
#pragma unroll
            for (int i = 0; i < 4; i++) {
                const float* xr0 = xwdB + ((size_t)(bg * 8 + bq * 4 + i) * TLEN + tB) * GDIM;
                xz[i] = __ldg(xr0 + u);
                xr[i] = __ldg(xr0 + UDIM + u);
                xh[i] = __ldg(xr0 + 2 * UDIM + u);
            }
        }
        rec_matvec(rzB, rrB, rhB, hpbB, red, kq, bq, j, sz, sr, sh);
        __syncthreads();   // BAR3

        if (kq == 0) {
#pragma unroll
            for (int q = 0; q < 3; q++) {
                const float* rp = red + ((q * 2 + bq) * 32 + j) * 12;
                float4 a = *(const float4*)(rp + 0);
                float4 b = *(const float4*)(rp + 4);
                float4 c = *(const float4*)(rp + 8);
                sz[0] += a.x; sz[1] += a.y; sz[2] += a.z; sz[3] += a.w;
                sr[0] += b.x; sr[1] += b.y; sr[2] += b.z; sr[3] += b.w;
                sh[0] += c.x; sh[1] += c.y; sh[2] += c.z; sh[3] += c.w;
            }
            float* gb = (s & 1) ? gbB1 : gbB0;
#pragma unroll
            for (int i = 0; i < 4; i++) {
                const int bL = bq * 4 + i;
                float z = fsig(xz[i] + rbzB + sz[i]);
                float r = fsig(xr[i] + rbrB + sr[i]);
                float hh = ftanh(xh[i] + rbhB + r * sh[i]);
                float hn = z * hprevB[i] + (1.f - z) * hh;
                hprevB[i] = hn;
                gb[bL * UDIM + u] = hn;
                if (layer == 1)
                    g_h1[((size_t)(bg * 8 + bL) * TLEN + tB) * (2 * UDIM) + UDIM + u] = hn;
                else if (s == TLEN - 1)
                    g_h2[(bg * 8 + bL) * 2 * UDIM + UDIM + u] = hn;
            }
            asm volatile("bar.sync 1, 64;" ::: "memory");
            if (tid == 0) red_release_gpu(cpB, 1u);
        }
        // poller warp: cpF released one matvec ago (drained); cpB skew
        // overlaps the kq0 warps' gates-B work above.
        if (tid == 128) {
            const unsigned tgt = 8u * (unsigned)(s + 1);
            while (ld_acquire_gpu(cpF) < tgt) __nanosleep(64);
            while (ld_acquire_gpu(cpB) < tgt) __nanosleep(64);
        }
        __syncthreads();   // BAR4: both chains' peer states visible

        // P5: warp-private reload of both chains' consumed slices (no BAR)
        {
            const float4* sF = (const float4*)((s & 1) ? gbF1 : gbF0);
            const float4* sB = (const float4*)((s & 1) ? gbB1 : gbB0);
            float4* dF = (float4*)hF;
            float4* dB = (float4*)hB;
            dF[qi0] = __ldcg(sF + qi0);
            dF[qi1] = __ldcg(sF + qi1);
            dB[qi0] = __ldcg(sB + qi0);
            dB[qi1] = __ldcg(sB + qi1);
        }
    }
}

// ======================== softmax head =================================
__global__ void out_kernel(const float* __restrict__ wout, const float* __restrict__ bout,
                           float* __restrict__ out)
{
    __shared__ float h[2 * UDIM];
    const int b = blockIdx.x, t = threadIdx.x;
    for (int i = t; i < 128; i += 32)
        ((float4*)h)[i] = ((const float4*)(g_h2 + b * 2 * UDIM))[i];
    __syncwarp();
    float l = -1e30f;
    if (t < CDIM) {
        float a = bout[t];
        for (int k = 0; k < 2 * UDIM; k++) a = fmaf(h[k], wout[k * CDIM + t], a);
        l = a;
    }
    float m = l;
    for (int o = 16; o; o >>= 1) m = fmaxf(m, __shfl_xor_sync(~0u, m, o));
    float e = (t < CDIM) ? expf(l - m) : 0.0f, ssum = e;
    for (int o = 16; o; o >>= 1) ssum += __shfl_xor_sync(~0u, ssum, o);
    if (t < CDIM) out[b * CDIM + t] = e / ssum;
}

// ========================= launcher ====================================
extern "C" void kernel_launch(void* const* d_in, const int* in_sizes, int n_in,
                              void* d_out, int out_size)
{
    const int*   x    = (const int*)d_in[0];
    const float* emb  = (const float*)d_in[1];
    const float* k1f  = (const float*)d_in[2];
    const float* rk1f = (const float*)d_in[3];
    const float* b1f  = (const float*)d_in[4];
    const float* k1b  = (const float*)d_in[5];
    const float* rk1b = (const float*)d_in[6];
    const float* b1b  = (const float*)d_in[7];
    const float* k2f  = (const float*)d_in[8];
    const float* rk2f = (const float*)d_in[9];
    const float* b2f  = (const float*)d_in[10];
    const float* k2b  = (const float*)d_in[11];
    const float* rk2b = (const float*)d_in[12];
    const float* b2b  = (const float*)d_in[13];
    const float* wout = (const float*)d_in[14];
    const float* bout = (const float*)d_in[15];
    float* out = (float*)d_out;
    (void)in_sizes; (void)n_in; (void)out_size;

    cudaFuncSetAttribute(rec_kernel, cudaFuncAttributeMaxDynamicSharedMemorySize, REC_SMEM);

    dim3 gg(GDIM / BN, (NB * TLEN) / BM, 2);
    gemm_kernel<<<gg, 256>>>(0, x, emb, k1f, k1b, b1f, b1b, EDIM, 0);
    rec_kernel<<<64, 256, REC_SMEM>>>(rk1f, rk1b, b1f + GDIM, b1b + GDIM, 1, 0);
    gemm_kernel<<<gg, 256>>>(1, x, emb, k2f, k2b, b2f, b2b, 2 * UDIM, 512);
    rec_kernel<<<64, 256, REC_SMEM>>>(rk2f, rk2b, b2f + GDIM, b2b + GDIM, 2, 512);
    out_kernel<<<NB, 32>>>(wout, bout, out);
}